// round 10
// baseline (speedup 1.0000x reference)
#include <cuda_runtime.h>

#define Hh 51
#define NB 4
#define NTH 224
#define BTOT 512
#define ROWF 104        // [0..50]=h1, [51]=x, [52..102]=h2, [103]=0 (single buffer)

__device__ __forceinline__ unsigned long long pack2(float lo, float hi) {
    unsigned long long r;
    asm("mov.b64 %0, {%1,%2};" : "=l"(r) : "f"(lo), "f"(hi));
    return r;
}
__device__ __forceinline__ void ffma2(unsigned long long &acc, unsigned long long a, unsigned long long b) {
    asm("fma.rn.f32x2 %0, %1, %2, %0;" : "+l"(acc) : "l"(a), "l"(b));
}
__device__ __forceinline__ float sum2(unsigned long long a) {
    float lo, hi;
    asm("mov.b64 {%0,%1}, %2;" : "=f"(lo), "=f"(hi) : "l"(a));
    return lo + hi;
}
__device__ __forceinline__ void lds128(unsigned long long &p0, unsigned long long &p1, unsigned addr) {
    asm volatile("ld.shared.v2.b64 {%0,%1}, [%2];" : "=l"(p0), "=l"(p1) : "r"(addr));
}
__device__ __forceinline__ float ftanh_(float x) {
    float r;
    asm("tanh.approx.f32 %0, %1;" : "=f"(r) : "f"(x));
    return r;
}
__device__ __forceinline__ float fsig(float x) {
    float r;
    asm("tanh.approx.f32 %0, %1;" : "=f"(r) : "f"(0.5f * x));
    return fmaf(0.5f, r, 0.5f);
}

// 4x4 transpose across lane bits 3..4 (gate <-> batch-slot).
__device__ __forceinline__ void transp4(float v[4], int lane) {
    {
        bool lo = lane & 8;
        float tA = lo ? v[0] : v[1];
        float tB = lo ? v[2] : v[3];
        tA = __shfl_xor_sync(0xffffffffu, tA, 8);
        tB = __shfl_xor_sync(0xffffffffu, tB, 8);
        if (lo) { v[0] = tA; v[2] = tB; } else { v[1] = tA; v[3] = tB; }
    }
    {
        bool hi = lane & 16;
        float uA = hi ? v[0] : v[2];
        float uB = hi ? v[1] : v[3];
        uA = __shfl_xor_sync(0xffffffffu, uA, 16);
        uB = __shfl_xor_sync(0xffffffffu, uB, 16);
        if (hi) { v[0] = uA; v[1] = uB; } else { v[2] = uA; v[3] = uB; }
    }
}

// Recompute a2[B..B+1] (h2-dot + joint-dot) and a1n[B..B+1] for batch pair B.
#define DOTS_PAIR(B) { \
    unsigned long long sA2 = pack2(bs2, 0.f), sB2 = pack2(bs2, 0.f); \
    _Pragma("unroll") for (int kk = 0; kk < 13; ++kk) { \
        unsigned long long u0, u1, u2, u3; \
        lds128(u0, u1, hb[(B)]     + 208u + kk * 16u); \
        lds128(u2, u3, hb[(B) + 1] + 208u + kk * 16u); \
        ffma2(sA2, w2p[26 + 2*kk], u0); ffma2(sA2, w2p[27 + 2*kk], u1); \
        ffma2(sB2, w2p[26 + 2*kk], u2); ffma2(sB2, w2p[27 + 2*kk], u3); } \
    unsigned long long sA1 = pack2(bs1, 0.f), sB1 = pack2(bs1, 0.f); \
    _Pragma("unroll") for (int kk = 0; kk < 13; ++kk) { \
        unsigned long long u0, u1, u2, u3; \
        lds128(u0, u1, hb[(B)]     + kk * 16u); \
        lds128(u2, u3, hb[(B) + 1] + kk * 16u); \
        ffma2(sA2, w2p[2*kk], u0); ffma2(sA2, w2p[2*kk + 1], u1); \
        ffma2(sA1, w1n[2*kk], u0); ffma2(sA1, w1n[2*kk + 1], u1); \
        ffma2(sB2, w2p[2*kk], u2); ffma2(sB2, w2p[2*kk + 1], u3); \
        ffma2(sB1, w1n[2*kk], u2); ffma2(sB1, w1n[2*kk + 1], u3); } \
    a2[(B)] = sA2; a2[(B) + 1] = sB2; a1n[(B)] = sA1; a1n[(B) + 1] = sB1; }

// Layer-2 cell update for pair B from carried a2 (writes h2 + pbuf).
#define TAIL2_PAIR(B) { \
    float v[4] = {0.f, 0.f, 0.f, 0.f}; \
    v[(B)]     = sum2(a2[(B)]); \
    v[(B) + 1] = sum2(a2[(B) + 1]); \
    transp4(v, lane); \
    if (act && (q >> 1) == ((B) >> 1)) { \
        float cg = fsig(v[1]) * c2 + fsig(v[0]) * ftanh_(v[2]); \
        c2 = cg; \
        float h2v = fsig(v[3]) * ftanh_(cg); \
        hcat[q][52 + j] = h2v; \
        pbuf[q][j] = wl * h2v; } }

// Layer-1 cell update for pair B from carried a1n + x (writes h1).
#define TAIL1_PAIR(B) { \
    float v[4] = {0.f, 0.f, 0.f, 0.f}; \
    v[(B)]     = fmaf(hcat[(B)][51],     wi1, sum2(a1n[(B)])); \
    v[(B) + 1] = fmaf(hcat[(B) + 1][51], wi1, sum2(a1n[(B) + 1])); \
    transp4(v, lane); \
    if (act && (q >> 1) == ((B) >> 1)) { \
        float cg = fsig(v[1]) * c1 + fsig(v[0]) * ftanh_(v[2]); \
        c1 = cg; \
        hcat[q][j] = fsig(v[3]) * ftanh_(cg); } }

#define REDUCE_PBUF(dst) { \
    float4 s4 = make_float4(0.f, 0.f, 0.f, 0.f); \
    const float4* p4 = (const float4*)&pbuf[q][0]; \
    _Pragma("unroll") for (int k = 0; k < 12; ++k) { \
        float4 v4 = p4[k]; \
        s4.x += v4.x; s4.y += v4.y; s4.z += v4.z; s4.w += v4.w; } \
    (dst) = (s4.x + s4.y) + (s4.z + s4.w) \
          + pbuf[q][48] + pbuf[q][49] + pbuf[q][50] + blin; }

__global__ void __launch_bounds__(NTH, 1)
lstm2_kernel(const float* __restrict__ input,
             const float* __restrict__ W_ih1, const float* __restrict__ W_hh1,
             const float* __restrict__ b_ih1, const float* __restrict__ b_hh1,
             const float* __restrict__ W_ih2, const float* __restrict__ W_hh2,
             const float* __restrict__ b_ih2, const float* __restrict__ b_hh2,
             const float* __restrict__ W_lin, const float* __restrict__ b_lin,
             float* __restrict__ out, int T, int Ttot)
{
    __shared__ __align__(16) float hcat[NB][ROWF];   // single buffer
    __shared__ __align__(16) float pbuf[NB][68];

    const int  tid  = threadIdx.x;
    const int  lane = tid & 31;
    const int  wid  = tid >> 5;
    const int  jloc = lane & 7;
    const int  q    = (lane >> 3) & 3;        // gate for dots; batch for update
    const int  j    = wid * 8 + jloc;
    const bool act  = (j < Hh);
    const int  b0   = blockIdx.x * NB;
    const int  row  = q * Hh + (act ? j : 0);

    const bool pre_lane = (wid == 6) && (jloc == 3);   // x prefetch, batch q
    const bool red_lane = (wid == 6) && (jloc == 4);   // out reduction, batch q

    for (int i = tid; i < NB * ROWF; i += NTH) (&hcat[0][0])[i] = 0.f;
    __syncthreads();                                   // order init before x(0) store
    if (tid < NB) hcat[tid][51] = input[(b0 + tid) * T];   // x(*,0)

    // ---- register-resident packed weights ----
    unsigned long long w1n[26], w2p[52];
    {
        const float* r1 = W_hh1 + row * Hh;
        #pragma unroll
        for (int k = 0; k < 26; ++k) {
            int k0 = 2*k, k1 = 2*k + 1;
            float a = (act && k0 < 51) ? r1[k0] : 0.f;
            float b = (act && k1 < 51) ? r1[k1] : 0.f;
            w1n[k] = pack2(a, b);
        }
        const float* ri = W_ih2 + row * Hh;   // multiplies h1
        const float* rh = W_hh2 + row * Hh;   // multiplies h2
        #pragma unroll
        for (int k = 0; k < 52; ++k) {
            int k0 = 2*k, k1 = 2*k + 1;
            float a = 0.f, b = 0.f;
            if (act) {
                a = (k0 < 51) ? ri[k0] : ((k0 >= 52 && k0 <= 102) ? rh[k0 - 52] : 0.f);
                b = (k1 < 51) ? ri[k1] : ((k1 >= 52 && k1 <= 102) ? rh[k1 - 52] : 0.f);
            }
            w2p[k] = pack2(a, b);
        }
    }
    const float wi1  = act ? W_ih1[row] : 0.f;
    const float bs1  = act ? (b_ih1[row] + b_hh1[row]) : 0.f;
    const float bs2  = act ? (b_ih2[row] + b_hh2[row]) : 0.f;
    const float wl   = act ? W_lin[j] : 0.f;
    const float blin = b_lin[0];

    unsigned hb[NB];
    #pragma unroll
    for (int b = 0; b < NB; ++b)
        hb[b] = (unsigned)__cvta_generic_to_shared(&hcat[b][0]);

    float c1 = 0.f, c2 = 0.f, xpre = 0.f;
    unsigned long long a1n[4], a2[4];
    #pragma unroll
    for (int b = 0; b < 4; ++b) { a1n[b] = pack2(bs1, 0.f); a2[b] = pack2(bs2, 0.f); }

    __syncthreads();

    // ================= pipelined main loop: pairs phase-shifted by one region =================
    // region 2s  : tails(p0, step s)   + dots(p1, step s-1)
    // region 2s+1: tails(p1, step s)   + dots(p0, step s)
    for (int s = 0; s <= T; ++s) {
        // ---------- region 2s ----------
        if (pre_lane && q < 2 && (s + 1) < T)              // LDG x(p0, s+1)
            xpre = input[(b0 + q) * T + (s + 1)];
        if (pre_lane && q >= 2 && s >= 1 && s < T)         // STS x(p1, s) (×0-benign vs p1 dots)
            hcat[q][51] = xpre;
        if (red_lane && q >= 2 && s >= 2) {                // out(p1, s-2)
            float sres; REDUCE_PBUF(sres);
            out[(b0 + q) * Ttot + (s - 2)] = sres;
        }
        if (s >= 1) TAIL2_PAIR(0)                          // tail2(p0, s-1) : carried a2
        if (s < T)  TAIL1_PAIR(0)                          // tail1(p0, s)   : carried a1n + x
        if (s >= 1) DOTS_PAIR(2)                           // dots(p1, s-1)
        __syncthreads();

        // ---------- region 2s+1 ----------
        if (pre_lane && q >= 2 && (s + 1) < T)             // LDG x(p1, s+1)
            xpre = input[(b0 + q) * T + (s + 1)];
        if (pre_lane && q < 2 && (s + 1) < T)              // STS x(p0, s+1)
            hcat[q][51] = xpre;
        if (red_lane && q < 2 && s >= 1 && s <= T - 1) {   // out(p0, s-1)
            float sres; REDUCE_PBUF(sres);
            out[(b0 + q) * Ttot + (s - 1)] = sres;
        }
        if (s >= 1) TAIL2_PAIR(2)                          // tail2(p1, s-1)
        if (s < T)  TAIL1_PAIR(2)                          // tail1(p1, s)
        if (s < T)  DOTS_PAIR(0)                           // dots(p0, s)
        __syncthreads();
    }

    // ---- flush: out(*, T-1) and x(T) feedback ----
    if (red_lane) {
        float sres; REDUCE_PBUF(sres);
        out[(b0 + q) * Ttot + (T - 1)] = sres;
        hcat[q][51] = sres;                                // x(T)
    }
    __syncthreads();

    // ================= autoregressive tail (lockstep, single buffer) =================
    for (int t = T; t < Ttot; ++t) {
        // phase A: layer-1 update from carried a1n + x(t); then h2-dot
        float v[4];
        #pragma unroll
        for (int b = 0; b < 4; ++b)
            v[b] = fmaf(hcat[b][51], wi1, sum2(a1n[b]));
        transp4(v, lane);
        if (act) {
            float cg = fsig(v[1]) * c1 + fsig(v[0]) * ftanh_(v[2]);
            c1 = cg;
            hcat[q][j] = fsig(v[3]) * ftanh_(cg);          // h1(t)
        }
        #pragma unroll
        for (int b = 0; b < 4; ++b) a2[b] = pack2(bs2, 0.f);
        #pragma unroll
        for (int kk = 0; kk < 13; ++kk) {
            #pragma unroll
            for (int b = 0; b < 4; ++b) {
                unsigned long long u0, u1;
                lds128(u0, u1, hb[b] + 208u + kk * 16u);
                ffma2(a2[b], w2p[26 + 2*kk], u0);
                ffma2(a2[b], w2p[27 + 2*kk], u1);
            }
        }
        __syncthreads();

        // phase B: joint dot over h1(t); layer-2 update
        #pragma unroll
        for (int b = 0; b < 4; ++b) a1n[b] = pack2(bs1, 0.f);
        #pragma unroll
        for (int kk = 0; kk < 13; ++kk) {
            #pragma unroll
            for (int b = 0; b < 4; ++b) {
                unsigned long long u0, u1;
                lds128(u0, u1, hb[b] + kk * 16u);
                ffma2(a2[b],  w2p[2*kk],     u0);
                ffma2(a2[b],  w2p[2*kk + 1], u1);
                ffma2(a1n[b], w1n[2*kk],     u0);
                ffma2(a1n[b], w1n[2*kk + 1], u1);
            }
        }
        #pragma unroll
        for (int b = 0; b < 4; ++b) v[b] = sum2(a2[b]);
        transp4(v, lane);
        if (act) {
            float cg = fsig(v[1]) * c2 + fsig(v[0]) * ftanh_(v[2]);
            c2 = cg;
            float h2v = fsig(v[3]) * ftanh_(cg);
            hcat[q][52 + j] = h2v;                         // h2(t)
            pbuf[q][j] = wl * h2v;
        }
        __syncthreads();

        // out(t) + x(t+1) feedback
        if (red_lane) {
            float sres; REDUCE_PBUF(sres);
            out[(b0 + q) * Ttot + t] = sres;
            if (t + 1 < Ttot) hcat[q][51] = sres;
        }
        __syncthreads();
    }
}

extern "C" void kernel_launch(void* const* d_in, const int* in_sizes, int n_in,
                              void* d_out, int out_size) {
    const float* input = (const float*)d_in[0];
    const float* W_ih1 = (const float*)d_in[1];
    const float* W_hh1 = (const float*)d_in[2];
    const float* b_ih1 = (const float*)d_in[3];
    const float* b_hh1 = (const float*)d_in[4];
    const float* W_ih2 = (const float*)d_in[5];
    const float* W_hh2 = (const float*)d_in[6];
    const float* b_ih2 = (const float*)d_in[7];
    const float* b_hh2 = (const float*)d_in[8];
    const float* W_lin = (const float*)d_in[9];
    const float* b_lin = (const float*)d_in[10];

    const int T    = in_sizes[0] / BTOT;   // 1024
    const int Ttot = out_size    / BTOT;   // 1088

    lstm2_kernel<<<BTOT / NB, NTH>>>(input, W_ih1, W_hh1, b_ih1, b_hh1,
                                     W_ih2, W_hh2, b_ih2, b_hh2,
                                     W_lin, b_lin,
                                     (float*)d_out, T, Ttot);
}

// round 11
// speedup vs baseline: 1.2841x; 1.2841x over previous
#include <cuda_runtime.h>

#define Hh 51
#define NB 4
#define NTH 224
#define BTOT 512
#define ROWF 104                        // [0..50]=h1, [51]=x, [52..102]=h2, [103]=0
#define BUF_BYTES (NB * ROWF * 4)       // bytes per double-buffer half

__device__ __forceinline__ unsigned long long pack2(float lo, float hi) {
    unsigned long long r;
    asm("mov.b64 %0, {%1,%2};" : "=l"(r) : "f"(lo), "f"(hi));
    return r;
}
__device__ __forceinline__ void ffma2(unsigned long long &acc, unsigned long long a, unsigned long long b) {
    asm("fma.rn.f32x2 %0, %1, %2, %0;" : "+l"(acc) : "l"(a), "l"(b));
}
__device__ __forceinline__ float sum2(unsigned long long a) {
    float lo, hi;
    asm("mov.b64 {%0,%1}, %2;" : "=f"(lo), "=f"(hi) : "l"(a));
    return lo + hi;
}
__device__ __forceinline__ void lds128(unsigned long long &p0, unsigned long long &p1, unsigned addr) {
    asm volatile("ld.shared.v2.b64 {%0,%1}, [%2];" : "=l"(p0), "=l"(p1) : "r"(addr));
}
__device__ __forceinline__ float ftanh_(float x) {
    float r;
    asm("tanh.approx.f32 %0, %1;" : "=f"(r) : "f"(x));
    return r;
}
__device__ __forceinline__ float fsig(float x) {
    float r;
    asm("tanh.approx.f32 %0, %1;" : "=f"(r) : "f"(0.5f * x));
    return fmaf(0.5f, r, 0.5f);
}

// 4x4 transpose across lane bits 3..4 (gate <-> batch-slot).
__device__ __forceinline__ void transp4(float v[4], int lane) {
    {
        bool lo = lane & 8;
        float tA = lo ? v[0] : v[1];
        float tB = lo ? v[2] : v[3];
        tA = __shfl_xor_sync(0xffffffffu, tA, 8);
        tB = __shfl_xor_sync(0xffffffffu, tB, 8);
        if (lo) { v[0] = tA; v[2] = tB; } else { v[1] = tA; v[3] = tB; }
    }
    {
        bool hi = lane & 16;
        float uA = hi ? v[0] : v[2];
        float uB = hi ? v[1] : v[3];
        uA = __shfl_xor_sync(0xffffffffu, uA, 16);
        uB = __shfl_xor_sync(0xffffffffu, uB, 16);
        if (hi) { v[0] = uA; v[1] = uB; } else { v[2] = uA; v[3] = uB; }
    }
}

#define REDUCE_PBUF(dst) { \
    float4 s4 = make_float4(0.f, 0.f, 0.f, 0.f); \
    const float4* p4 = (const float4*)&pbuf[q][0]; \
    _Pragma("unroll") for (int k = 0; k < 12; ++k) { \
        float4 v4 = p4[k]; \
        s4.x += v4.x; s4.y += v4.y; s4.z += v4.z; s4.w += v4.w; } \
    (dst) = (s4.x + s4.y) + (s4.z + s4.w) \
          + pbuf[q][48] + pbuf[q][49] + pbuf[q][50] + blin; }

// One full timestep. CO/PO are COMPILE-TIME buffer byte-offsets; CI/PI buffer indices.
#define STEP(t, CI, PI, CO, PO) { \
    /* spare duties (warp 6), overlapped with phase A */ \
    if (pre_lane && ((t) + 1 < T)) \
        xpre = input[(b0 + q) * T + ((t) + 1)]; \
    if (red_lane && (t) >= 1 && (t) < T) { \
        float sres; REDUCE_PBUF(sres); \
        out[(b0 + q) * Ttot + ((t) - 1)] = sres; \
    } \
    /* tail-1 FIRST (independent of phase-A dot): layer-1 update from carried a1n + x(t) */ \
    float v[4]; \
    _Pragma("unroll") for (int b = 0; b < NB; ++b) \
        v[b] = fmaf(hcat[PI][b][51], wi1, sum2(a1n[b])); \
    transp4(v, lane); \
    { \
        float cg = fsig(v[1]) * c1 + fsig(v[0]) * ftanh_(v[2]); \
        c1 = cg; \
        float h1 = fsig(v[3]) * ftanh_(cg); \
        if (act) hcat[CI][q][j] = h1; \
    } \
    /* phase-A dot: a2 = bs2 + W_hh2 . h2(t-1)  (prev slots 52..103, static offsets) */ \
    unsigned long long a2[NB]; \
    _Pragma("unroll") for (int b = 0; b < NB; ++b) a2[b] = pack2(bs2, 0.f); \
    _Pragma("unroll") for (int kk = 0; kk < 13; ++kk) { \
        _Pragma("unroll") for (int b = 0; b < NB; ++b) { \
            unsigned long long q0, q1; \
            lds128(q0, q1, hb[b] + (PO) + 208u + kk * 16u); \
            ffma2(a2[b], w2p[26 + 2*kk], q0); \
            ffma2(a2[b], w2p[27 + 2*kk], q1); \
        } \
    } \
    __syncthreads();  /* B_A */ \
    /* phase B */ \
    if (pre_lane && ((t) + 1 < T)) hcat[CI][q][51] = xpre; \
    _Pragma("unroll") for (int b = 0; b < NB; ++b) a1n[b] = pack2(bs1, 0.f); \
    _Pragma("unroll") for (int kk = 0; kk < 13; ++kk) { \
        _Pragma("unroll") for (int b = 0; b < NB; ++b) { \
            unsigned long long p0, p1; \
            lds128(p0, p1, hb[b] + (CO) + kk * 16u); \
            ffma2(a2[b],  w2p[2*kk],     p0); \
            ffma2(a2[b],  w2p[2*kk + 1], p1); \
            ffma2(a1n[b], w1n[2*kk],     p0); \
            ffma2(a1n[b], w1n[2*kk + 1], p1); \
        } \
    } \
    _Pragma("unroll") for (int b = 0; b < NB; ++b) v[b] = sum2(a2[b]); \
    transp4(v, lane); \
    { \
        float cg = fsig(v[1]) * c2 + fsig(v[0]) * ftanh_(v[2]); \
        c2 = cg; \
        float h2v = fsig(v[3]) * ftanh_(cg); \
        if (act) { \
            hcat[CI][q][52 + j] = h2v; \
            pbuf[q][j] = wl * h2v; \
        } \
    } \
    __syncthreads();  /* B_B */ \
    /* autoregressive feedback: out(t) -> x(t+1) */ \
    if ((t) >= T - 1) { \
        if (red_lane) { \
            float sres; REDUCE_PBUF(sres); \
            out[(b0 + q) * Ttot + (t)] = sres; \
            hcat[CI][q][51] = sres; \
        } \
        __syncthreads();  /* B_C */ \
    } \
}

__global__ void __launch_bounds__(NTH, 1)
lstm2_kernel(const float* __restrict__ input,
             const float* __restrict__ W_ih1, const float* __restrict__ W_hh1,
             const float* __restrict__ b_ih1, const float* __restrict__ b_hh1,
             const float* __restrict__ W_ih2, const float* __restrict__ W_hh2,
             const float* __restrict__ b_ih2, const float* __restrict__ b_hh2,
             const float* __restrict__ W_lin, const float* __restrict__ b_lin,
             float* __restrict__ out, int T, int Ttot)
{
    __shared__ __align__(16) float hcat[2][NB][ROWF];   // double-buffered
    __shared__ __align__(16) float pbuf[NB][68];

    const int  tid  = threadIdx.x;
    const int  lane = tid & 31;
    const int  wid  = tid >> 5;
    const int  jloc = lane & 7;
    const int  q    = (lane >> 3) & 3;          // gate index for dots; batch index for update
    const int  j    = wid * 8 + jloc;
    const bool act  = (j < Hh);
    const int  b0   = blockIdx.x * NB;
    const int  row  = q * Hh + (act ? j : 0);

    const bool pre_lane = (wid == 6) && (jloc == 3);    // x(t+1) prefetch, batch q
    const bool red_lane = (wid == 6) && (jloc == 4);    // output reduction, batch q

    for (int i = tid; i < 2 * NB * ROWF; i += NTH) (&hcat[0][0][0])[i] = 0.f;
    __syncthreads();                                    // order init before x(0) store
    if (tid < NB) hcat[1][tid][51] = input[(b0 + tid) * T];   // x(0) into prev-buffer of t=0

    // ---- weights, packed along K into 64-bit pairs (registers) ----
    unsigned long long w1n[26], w2p[52];
    {
        const float* r1 = W_hh1 + row * Hh;
        #pragma unroll
        for (int k = 0; k < 26; ++k) {
            int k0 = 2*k, k1 = 2*k + 1;
            float a = (act && k0 < 51) ? r1[k0] : 0.f;
            float b = (act && k1 < 51) ? r1[k1] : 0.f;
            w1n[k] = pack2(a, b);
        }
        const float* ri = W_ih2 + row * Hh;   // multiplies h1
        const float* rh = W_hh2 + row * Hh;   // multiplies h2
        #pragma unroll
        for (int k = 0; k < 52; ++k) {
            int k0 = 2*k, k1 = 2*k + 1;
            float a = 0.f, b = 0.f;
            if (act) {
                a = (k0 < 51) ? ri[k0] : ((k0 >= 52 && k0 <= 102) ? rh[k0 - 52] : 0.f);
                b = (k1 < 51) ? ri[k1] : ((k1 >= 52 && k1 <= 102) ? rh[k1 - 52] : 0.f);
            }
            w2p[k] = pack2(a, b);
        }
    }
    const float wi1  = act ? W_ih1[row] : 0.f;
    const float bs1  = act ? (b_ih1[row] + b_hh1[row]) : 0.f;
    const float bs2  = act ? (b_ih2[row] + b_hh2[row]) : 0.f;
    const float wl   = act ? W_lin[j] : 0.f;
    const float blin = b_lin[0];

    unsigned hb[NB];
    #pragma unroll
    for (int b = 0; b < NB; ++b)
        hb[b] = (unsigned)__cvta_generic_to_shared(&hcat[0][b][0]);

    float c1 = 0.f, c2 = 0.f, xpre = 0.f;
    unsigned long long a1n[NB];
    #pragma unroll
    for (int b = 0; b < NB; ++b) a1n[b] = pack2(bs1, 0.f);   // layer-1 gates for t=0 (W_hh1·0)

    __syncthreads();

    // time loop unrolled by 2: even t -> cur buf0/prev buf1; odd t -> cur buf1/prev buf0
    for (int t = 0; t < Ttot; t += 2) {
        STEP(t,     0, 1, 0u,                   (unsigned)BUF_BYTES)
        STEP(t + 1, 1, 0, (unsigned)BUF_BYTES,  0u)
    }
}

extern "C" void kernel_launch(void* const* d_in, const int* in_sizes, int n_in,
                              void* d_out, int out_size) {
    const float* input = (const float*)d_in[0];
    const float* W_ih1 = (const float*)d_in[1];
    const float* W_hh1 = (const float*)d_in[2];
    const float* b_ih1 = (const float*)d_in[3];
    const float* b_hh1 = (const float*)d_in[4];
    const float* W_ih2 = (const float*)d_in[5];
    const float* W_hh2 = (const float*)d_in[6];
    const float* b_ih2 = (const float*)d_in[7];
    const float* b_hh2 = (const float*)d_in[8];
    const float* W_lin = (const float*)d_in[9];
    const float* b_lin = (const float*)d_in[10];

    const int T    = in_sizes[0] / BTOT;   // 1024
    const int Ttot = out_size    / BTOT;   // 1088 (even)

    lstm2_kernel<<<BTOT / NB, NTH>>>(input, W_ih1, W_hh1, b_ih1, b_hh1,
                                     W_ih2, W_hh2, b_ih2, b_hh2,
                                     W_lin, b_lin,
                                     (float*)d_out, T, Ttot);
}